// round 12
// baseline (speedup 1.0000x reference)
#include <cuda_runtime.h>
#include <cuda_pipeline.h>
#include <cstdint>

// Problem constants (fixed by the reference)
#define B 16
#define S 4096
#define H 768
#define NUM_WORDS 2048          // S/2
#define H4 (H / 4)              // 192 float4 lanes per row
#define TT 32                   // tokens owned per block
#define NT 128                  // blocks per batch row (covers tokens 1..4095)
#define WW (NUM_WORDS / NT)     // 16: static zero-fill words per block
#define T 4                     // tokens per pipeline stage
#define NSTG 3                  // ring depth (3 x 12 KB = 36 KB)
#define STG_F4 (T * H4)         // float4 elements per stage (768 = 12KB)
#define WIN (TT + 2)            // wid window: positions t0-1 .. t0+TT

// Fused single kernel, one block per (batch, 32-token chunk).
// Payload pipeline is fully PER-THREAD (no block barriers on the hot path):
// each thread's cp.async writes only smem cells {j*H4 + tid} and only that
// thread reads them. 3-deep per-thread ring of 4-token stages.
__global__ __launch_bounds__(H4) void fused_word_mean_kernel(
    const float* __restrict__ hidden,   // [B, S, H]
    const int*   __restrict__ word_ids, // [B, S]
    float*       __restrict__ out)      // [B, NUM_WORDS, H]
{
    __shared__ float4 s_buf[NSTG][STG_F4];  // 36 KB
    __shared__ int s_wid[WIN];
    __shared__ int s_endtab[TT];
    __shared__ int s_meta[4];               // nwords, s_first, w_first, e_last

    const int blk = blockIdx.x;
    const int b   = blk / NT;
    const int tc  = blk % NT;
    const int t0  = 1 + tc * TT;
    const int t_range_end = min(t0 + TT, S - 1);
    const int tid = threadIdx.x;            // 0..191
    const int* __restrict__ wrow = word_ids + b * S;

    // ---- load wid window [t0-1 .. t0+TT] ----
    if (tid < WIN) {
        const int p = t0 - 1 + tid;
        s_wid[tid] = (p < S) ? wrow[p] : -1;
    }

    // ---- independent zero-fill for absent words, overlapped with prologue ----
    const int wmax = __ldg(wrow + (S - 2));
    const int wz0  = tc * WW;
    if (wz0 + WW - 1 > wmax) {
        float4* __restrict__ zrow =
            reinterpret_cast<float4*>(out) + (size_t)b * NUM_WORDS * H4 + tid;
        const float4 z = make_float4(0.f, 0.f, 0.f, 0.f);
        #pragma unroll
        for (int k2 = 0; k2 < WW; ++k2) {
            const int w = wz0 + k2;
            if (w > wmax) __stcs(&zrow[(size_t)w * H4], z);
        }
    }
    __syncthreads();

    // ---- warp 0: build local boundary table (words STARTING in range) ----
    if (tid < 32) {
        const int i = tid;                   // token p = t0 + i
        const int p = t0 + i;
        const int w_i    = s_wid[i + 1];
        const int prev_i = s_wid[i];
        const bool is_start = (p < t_range_end) && (w_i != prev_i);
        const unsigned mask = __ballot_sync(0xffffffffu, is_start);
        const int nwords = __popc(mask);
        if (is_start) {
            const int rank = __popc(mask & ((1u << i) - 1));
            int end;
            const unsigned higher = mask & ~((i < 31) ? ((2u << i) - 1) : 0xffffffffu);
            if (higher) {
                end = t0 + __ffs(higher) - 1;     // next start = this word's end
            } else {
                // last word starting in range: scan forward (terminates at
                // latest at wid[S-1] == -1)
                int q = p + 1;
                while (true) {
                    const int wi = q - (t0 - 1);
                    const int wq = (wi < WIN) ? s_wid[wi] : __ldg(wrow + q);
                    if (wq != w_i) break;
                    ++q;
                }
                end = q;
            }
            s_endtab[rank] = end;
            if (rank == 0) { s_meta[1] = p; s_meta[2] = w_i; }
            if (rank == nwords - 1) s_meta[3] = end;
        }
        if (i == 0) s_meta[0] = nwords;
    }
    __syncthreads();    // table ready; last block-wide barrier

    const int nwords = s_meta[0];
    if (nwords <= 0) return;

    const int s_first = s_meta[1];
    const int w_first = s_meta[2];
    const int e_last  = s_meta[3];
    const int n_tok   = e_last - s_first;

    const float4* __restrict__ src =
        reinterpret_cast<const float4*>(hidden) + ((size_t)b * S + s_first) * H4;
    float4* __restrict__ outBase =
        reinterpret_cast<float4*>(out) + ((size_t)b * NUM_WORDS + w_first) * H4 + tid;

    const int total_f4 = n_tok * H4;
    const int n_stages = (n_tok + T - 1) / T;

    // ---- prime the per-thread ring: issue up to NSTG stages ----
    #pragma unroll
    for (int ps = 0; ps < NSTG; ++ps) {
        if (ps < n_stages) {
            const int base = ps * STG_F4;
            #pragma unroll
            for (int i = 0; i < T; ++i) {
                const int idx = i * H4 + tid;
                const int g   = base + idx;
                if (g < total_f4)
                    __pipeline_memcpy_async(&s_buf[ps][idx], &src[g], sizeof(float4));
            }
            __pipeline_commit();
        }
    }
    // Pad commits so in-flight group count is always NSTG (wait math stays uniform).
    #pragma unroll
    for (int ps = n_stages; ps < NSTG; ++ps) __pipeline_commit();

    int k = 0;
    int e_cur = s_endtab[0];
    int s_cur = s_first;
    float4 acc = make_float4(0.f, 0.f, 0.f, 0.f);
    int ring = 0;

    for (int s = 0; s < n_stages; ++s) {
        // wait for THIS thread's stage-s group (NSTG-1 newer groups pending)
        __pipeline_wait_prior(NSTG - 1);

        const float4* __restrict__ buf = s_buf[ring];
        #pragma unroll
        for (int j = 0; j < T; ++j) {
            const int t = s_first + s * T + j;
            if (t < e_last) {            // uniform across block
                const float4 v = buf[j * H4 + tid];
                if (t == e_cur) {        // word k complete -> emit mean
                    const int c = e_cur - s_cur;
                    const float inv = __fdividef(1.0f, (float)c);
                    float4 r;
                    r.x = acc.x * inv; r.y = acc.y * inv;
                    r.z = acc.z * inv; r.w = acc.w * inv;
                    __stcs(&outBase[k * H4], r);
                    s_cur = e_cur;
                    ++k;
                    e_cur = s_endtab[k < nwords ? k : nwords - 1];
                    acc = make_float4(0.f, 0.f, 0.f, 0.f);
                }
                acc.x += v.x; acc.y += v.y;
                acc.z += v.z; acc.w += v.w;
            }
        }

        // refill this ring slot with stage s+NSTG (thread's own cells only;
        // its reads above already retired before new data can land)
        {
            const int base = (s + NSTG) * STG_F4;
            if (s + NSTG < n_stages) {
                float4* dst = s_buf[ring];
                #pragma unroll
                for (int i = 0; i < T; ++i) {
                    const int idx = i * H4 + tid;
                    const int g   = base + idx;
                    if (g < total_f4)
                        __pipeline_memcpy_async(&dst[idx], &src[g], sizeof(float4));
                }
            }
            __pipeline_commit();   // always commit: keeps group accounting uniform
        }

        ring = (ring + 1 < NSTG) ? ring + 1 : 0;
    }

    // Last word (its end == e_last is never reached inside the loop).
    {
        const int c = e_last - s_cur;
        const float inv = __fdividef(1.0f, (float)(c > 0 ? c : 1));
        float4 r;
        r.x = acc.x * inv; r.y = acc.y * inv;
        r.z = acc.z * inv; r.w = acc.w * inv;
        __stcs(&outBase[(nwords - 1) * H4], r);
    }
}

extern "C" void kernel_launch(void* const* d_in, const int* in_sizes, int n_in,
                              void* d_out, int out_size)
{
    const float* hidden   = (const float*)d_in[0];  // [B,S,H] float32
    const int*   word_ids = (const int*)d_in[1];    // [B,S] int32
    float*       out      = (float*)d_out;          // [B,NUM_WORDS,H] float32

    (void)in_sizes; (void)n_in; (void)out_size;

    fused_word_mean_kernel<<<B * NT, H4>>>(hidden, word_ids, out);
}

// round 13
// speedup vs baseline: 1.0092x; 1.0092x over previous
#include <cuda_runtime.h>
#include <cuda_pipeline.h>
#include <cstdint>

// Problem constants (fixed by the reference)
#define B 16
#define S 4096
#define H 768
#define NUM_WORDS 2048          // S/2
#define H4 (H / 4)              // 192 float4 lanes per row
#define TT 32                   // tokens owned per block
#define NT 128                  // blocks per batch row (covers tokens 1..4095)
#define WW (NUM_WORDS / NT)     // 16: static zero-fill words per block
#define T 4                     // tokens per pipeline stage
#define NSTG 3                  // ring depth (3 x 12 KB = 36 KB)
#define STG_F4 (T * H4)         // float4 elements per stage (768 = 12KB)
#define WIN (TT + 2)            // wid window: positions t0-1 .. t0+TT

// Fused single kernel, one block per (batch, 32-token chunk).
// Payload pipeline is fully PER-THREAD (no block barriers on the hot path):
// each thread's cp.async writes only smem cells {j*H4 + tid} and only that
// thread reads them. 3-deep per-thread ring of 4-token stages.
__global__ __launch_bounds__(H4) void fused_word_mean_kernel(
    const float* __restrict__ hidden,   // [B, S, H]
    const int*   __restrict__ word_ids, // [B, S]
    float*       __restrict__ out)      // [B, NUM_WORDS, H]
{
    __shared__ float4 s_buf[NSTG][STG_F4];  // 36 KB
    __shared__ int s_wid[WIN];
    __shared__ int s_endtab[TT];
    __shared__ int s_meta[4];               // nwords, s_first, w_first, e_last

    const int blk = blockIdx.x;
    const int b   = blk / NT;
    const int tc  = blk % NT;
    const int t0  = 1 + tc * TT;
    const int t_range_end = min(t0 + TT, S - 1);
    const int tid = threadIdx.x;            // 0..191
    const int* __restrict__ wrow = word_ids + b * S;

    // ---- load wid window [t0-1 .. t0+TT] ----
    if (tid < WIN) {
        const int p = t0 - 1 + tid;
        s_wid[tid] = (p < S) ? wrow[p] : -1;
    }

    // ---- independent zero-fill for absent words, overlapped with prologue ----
    const int wmax = __ldg(wrow + (S - 2));
    const int wz0  = tc * WW;
    if (wz0 + WW - 1 > wmax) {
        float4* __restrict__ zrow =
            reinterpret_cast<float4*>(out) + (size_t)b * NUM_WORDS * H4 + tid;
        const float4 z = make_float4(0.f, 0.f, 0.f, 0.f);
        #pragma unroll
        for (int k2 = 0; k2 < WW; ++k2) {
            const int w = wz0 + k2;
            if (w > wmax) __stcs(&zrow[(size_t)w * H4], z);
        }
    }
    __syncthreads();

    // ---- warp 0: build local boundary table (words STARTING in range) ----
    if (tid < 32) {
        const int i = tid;                   // token p = t0 + i
        const int p = t0 + i;
        const int w_i    = s_wid[i + 1];
        const int prev_i = s_wid[i];
        const bool is_start = (p < t_range_end) && (w_i != prev_i);
        const unsigned mask = __ballot_sync(0xffffffffu, is_start);
        const int nwords = __popc(mask);
        if (is_start) {
            const int rank = __popc(mask & ((1u << i) - 1));
            int end;
            const unsigned higher = mask & ~((i < 31) ? ((2u << i) - 1) : 0xffffffffu);
            if (higher) {
                end = t0 + __ffs(higher) - 1;     // next start = this word's end
            } else {
                // last word starting in range: scan forward (terminates at
                // latest at wid[S-1] == -1)
                int q = p + 1;
                while (true) {
                    const int wi = q - (t0 - 1);
                    const int wq = (wi < WIN) ? s_wid[wi] : __ldg(wrow + q);
                    if (wq != w_i) break;
                    ++q;
                }
                end = q;
            }
            s_endtab[rank] = end;
            if (rank == 0) { s_meta[1] = p; s_meta[2] = w_i; }
            if (rank == nwords - 1) s_meta[3] = end;
        }
        if (i == 0) s_meta[0] = nwords;
    }
    __syncthreads();    // table ready; last block-wide barrier

    const int nwords = s_meta[0];
    if (nwords <= 0) return;

    const int s_first = s_meta[1];
    const int w_first = s_meta[2];
    const int e_last  = s_meta[3];
    const int n_tok   = e_last - s_first;

    const float4* __restrict__ src =
        reinterpret_cast<const float4*>(hidden) + ((size_t)b * S + s_first) * H4;
    float4* __restrict__ outBase =
        reinterpret_cast<float4*>(out) + ((size_t)b * NUM_WORDS + w_first) * H4 + tid;

    const int total_f4 = n_tok * H4;
    const int n_stages = (n_tok + T - 1) / T;

    // ---- prime the per-thread ring: issue up to NSTG stages ----
    #pragma unroll
    for (int ps = 0; ps < NSTG; ++ps) {
        if (ps < n_stages) {
            const int base = ps * STG_F4;
            #pragma unroll
            for (int i = 0; i < T; ++i) {
                const int idx = i * H4 + tid;
                const int g   = base + idx;
                if (g < total_f4)
                    __pipeline_memcpy_async(&s_buf[ps][idx], &src[g], sizeof(float4));
            }
            __pipeline_commit();
        }
    }
    // Pad commits so in-flight group count is always NSTG (wait math stays uniform).
    #pragma unroll
    for (int ps = n_stages; ps < NSTG; ++ps) __pipeline_commit();

    int k = 0;
    int e_cur = s_endtab[0];
    int s_cur = s_first;
    float4 acc = make_float4(0.f, 0.f, 0.f, 0.f);
    int ring = 0;

    for (int s = 0; s < n_stages; ++s) {
        // wait for THIS thread's stage-s group (NSTG-1 newer groups pending)
        __pipeline_wait_prior(NSTG - 1);

        const float4* __restrict__ buf = s_buf[ring];
        #pragma unroll
        for (int j = 0; j < T; ++j) {
            const int t = s_first + s * T + j;
            if (t < e_last) {            // uniform across block
                const float4 v = buf[j * H4 + tid];
                if (t == e_cur) {        // word k complete -> emit mean
                    const int c = e_cur - s_cur;
                    const float inv = __fdividef(1.0f, (float)c);
                    float4 r;
                    r.x = acc.x * inv; r.y = acc.y * inv;
                    r.z = acc.z * inv; r.w = acc.w * inv;
                    __stcs(&outBase[k * H4], r);
                    s_cur = e_cur;
                    ++k;
                    e_cur = s_endtab[k < nwords ? k : nwords - 1];
                    acc = make_float4(0.f, 0.f, 0.f, 0.f);
                }
                acc.x += v.x; acc.y += v.y;
                acc.z += v.z; acc.w += v.w;
            }
        }

        // refill this ring slot with stage s+NSTG (thread's own cells only;
        // its reads above already retired before new data can land)
        {
            const int base = (s + NSTG) * STG_F4;
            if (s + NSTG < n_stages) {
                float4* dst = s_buf[ring];
                #pragma unroll
                for (int i = 0; i < T; ++i) {
                    const int idx = i * H4 + tid;
                    const int g   = base + idx;
                    if (g < total_f4)
                        __pipeline_memcpy_async(&dst[idx], &src[g], sizeof(float4));
                }
            }
            __pipeline_commit();   // always commit: keeps group accounting uniform
        }

        ring = (ring + 1 < NSTG) ? ring + 1 : 0;
    }

    // Last word (its end == e_last is never reached inside the loop).
    {
        const int c = e_last - s_cur;
        const float inv = __fdividef(1.0f, (float)(c > 0 ? c : 1));
        float4 r;
        r.x = acc.x * inv; r.y = acc.y * inv;
        r.z = acc.z * inv; r.w = acc.w * inv;
        __stcs(&outBase[(nwords - 1) * H4], r);
    }
}

extern "C" void kernel_launch(void* const* d_in, const int* in_sizes, int n_in,
                              void* d_out, int out_size)
{
    const float* hidden   = (const float*)d_in[0];  // [B,S,H] float32
    const int*   word_ids = (const int*)d_in[1];    // [B,S] int32
    float*       out      = (float*)d_out;          // [B,NUM_WORDS,H] float32

    (void)in_sizes; (void)n_in; (void)out_size;

    fused_word_mean_kernel<<<B * NT, H4>>>(hidden, word_ids, out);
}